// round 15
// baseline (speedup 1.0000x reference)
#include <cuda_runtime.h>
#include <cuda_bf16.h>
#include <stdint.h>
#include <math.h>

#define B_    64
#define T_    8192
#define DIN   20
#define NROWS ((size_t)B_ * T_)
#define WARM  512
#define NTILES2 2048
#define NBLK   148

// device scratch: packed (q_fast, q_slow)
__device__ float2 g_qfs[NROWS];
// pre-split weight planes (bf16 hi/lo)
__device__ __align__(16) __nv_bfloat16 g_w1h[128 * 24];
__device__ __align__(16) __nv_bfloat16 g_w1l[128 * 24];
__device__ __align__(16) __nv_bfloat16 g_w2h[128 * 136];
__device__ __align__(16) __nv_bfloat16 g_w2l[128 * 136];

// ---------------------------------------------------------------------------
__device__ __forceinline__ void mma16(float* d, const uint32_t* a, const uint32_t* b) {
    asm("mma.sync.aligned.m16n8k16.row.col.f32.bf16.bf16.f32 "
        "{%0,%1,%2,%3}, {%4,%5,%6,%7}, {%8,%9}, {%0,%1,%2,%3};"
        : "+f"(d[0]), "+f"(d[1]), "+f"(d[2]), "+f"(d[3])
        : "r"(a[0]), "r"(a[1]), "r"(a[2]), "r"(a[3]), "r"(b[0]), "r"(b[1]));
}
__device__ __forceinline__ void mma8b(float* d, const uint32_t* a, const uint32_t* b) {
    asm("mma.sync.aligned.m16n8k8.row.col.f32.bf16.bf16.f32 "
        "{%0,%1,%2,%3}, {%4,%5}, {%6}, {%0,%1,%2,%3};"
        : "+f"(d[0]), "+f"(d[1]), "+f"(d[2]), "+f"(d[3])
        : "r"(a[0]), "r"(a[1]), "r"(b[0]));
}
__device__ __forceinline__ void ldsm4(uint32_t* R, uint32_t addr) {
    asm volatile("ldmatrix.sync.aligned.m8n8.x4.shared.b16 {%0,%1,%2,%3},[%4];"
        : "=r"(R[0]), "=r"(R[1]), "=r"(R[2]), "=r"(R[3]) : "r"(addr));
}
__device__ __forceinline__ void ldsm2(uint32_t* R, uint32_t addr) {
    asm volatile("ldmatrix.sync.aligned.m8n8.x2.shared.b16 {%0,%1},[%2];"
        : "=r"(R[0]), "=r"(R[1]) : "r"(addr));
}
__device__ __forceinline__ void ldsm1(uint32_t* R, uint32_t addr) {
    asm volatile("ldmatrix.sync.aligned.m8n8.x1.shared.b16 {%0},[%1];"
        : "=r"(R[0]) : "r"(addr));
}
__device__ __forceinline__ void cpasync16(uint32_t saddr, const void* g) {
    asm volatile("cp.async.cg.shared.global [%0], [%1], 16;" :: "r"(saddr), "l"(g));
}
// fast tanh-form GELU (5 FMA/ALU + 2 MUFU, branch-free)
__device__ __forceinline__ float gelu_fast(float x) {
    float x2   = x * x;
    float q    = fmaf(-0.10294419f, x2, -2.3021177f);
    float narg = x * q;
    float e2;
    asm("ex2.approx.f32 %0, %1;" : "=f"(e2) : "f"(narg));
    float d = 1.0f + e2;
    float r;
    asm("rcp.approx.f32 %0, %1;" : "=f"(r) : "f"(d));
    return x * r;
}
__device__ __forceinline__ float sigmoid_fast(float x) {
    float e2;
    asm("ex2.approx.f32 %0, %1;" : "=f"(e2) : "f"(-1.4426950408889634f * x));
    float r;
    asm("rcp.approx.f32 %0, %1;" : "=f"(r) : "f"(1.0f + e2));
    return r;
}
__device__ __forceinline__ void split2_bf16(float x0, float x1,
                                            uint32_t& hi, uint32_t& lo) {
    uint32_t h;
    asm("cvt.rn.bf16x2.f32 %0, %1, %2;" : "=r"(h) : "f"(x1), "f"(x0));
    float h0 = __uint_as_float(h << 16);
    float h1 = __uint_as_float(h & 0xffff0000u);
    float r0 = x0 - h0, r1 = x1 - h1;
    asm("cvt.rn.bf16x2.f32 %0, %1, %2;" : "=r"(lo) : "f"(r1), "f"(r0));
    hi = h;
}

// ---------------------------------------------------------------------------
// Kernel A: gate + EMA + folded weight pre-split. Writes packed (qf, qs).
// ---------------------------------------------------------------------------
__global__ void __launch_bounds__(256) ema_kernel(
    const float* __restrict__ gaze,
    const float* __restrict__ p_logthr, const float* __restrict__ p_invT,
    const float* __restrict__ W1, const float* __restrict__ W2,
    float2* __restrict__ qfs_o)
{
    extern __shared__ float sm[];
    float2* sg  = reinterpret_cast<float2*>(sm);
    float*  sga = sm + 5124;
    float*  sqf = sga + 2560;
    float*  sqs = sqf + 2560;
    float*  scn = sqs + 2560;

    const int tid = threadIdx.x;

    {   // weight prep
        int i = blockIdx.x * 256 + tid;
        if (i < 128 * 136) {
            int n = i / 136, k = i - n * 136;
            float v = (k < 128) ? W2[k * 128 + n] : 0.0f;
            __nv_bfloat16 h = __float2bfloat16_rn(v);
            g_w2h[i] = h;
            g_w2l[i] = __float2bfloat16_rn(v - __bfloat162float(h));
        }
        if (i < 128 * 24) {
            int n = i / 24, k = i - n * 24;
            float v = (k < DIN) ? W1[k * 128 + n] : 0.0f;
            __nv_bfloat16 h = __float2bfloat16_rn(v);
            g_w1h[i] = h;
            g_w1l[i] = __float2bfloat16_rn(v - __bfloat162float(h));
        }
    }

    const int row = blockIdx.x >> 2;
    const int t0  = (blockIdx.x & 3) * 2048;
    const int ts  = max(t0 - WARM, 0);
    const int ts2 = max(ts - 1, 0);
    const int E   = t0 + 2048 - ts;
    const int NG  = t0 + 2048 - ts2;
    const int hof = ts - ts2;

    const float2* gz = reinterpret_cast<const float2*>(gaze) + (size_t)row * T_;
    for (int i = tid; i < NG; i += 256) sg[i] = gz[ts2 + i];
    const float thr  = expf(p_logthr[0]);
    const float invT = p_invT[0];
    const float inv_dt = 240.0f;
    __syncthreads();

    const int CH = (E + 255) >> 8;
    float Af = 1.0f, Bf = 0.0f, As = 1.0f, Bs = 0.0f;
    for (int i = 0; i < CH; i++) {
        int e = tid * CH + i;
        if (e < E) {
            int j = e + hof;
            float2 xc = sg[j];
            float2 x1 = sg[max(j - 1, 0)];
            float vx = (xc.x - x1.x) * inv_dt;
            float vy = (xc.y - x1.y) * inv_dt;
            float sp = sqrtf(vx * vx + vy * vy);
            float g  = 1.0f / (1.0f + expf(-invT * (sp - thr)));
            sga[e] = g;
            Bf = 0.8f  * Bf + 0.2f  * g;  Af *= 0.8f;
            Bs = 0.95f * Bs + 0.05f * g;  As *= 0.95f;
        }
    }
    const unsigned full = 0xffffffffu;
    const int lane = tid & 31, warp = tid >> 5;
    float iAf = Af, iBf = Bf, iAs = As, iBs = Bs;
#pragma unroll
    for (int d = 1; d < 32; d <<= 1) {
        float pa = __shfl_up_sync(full, iAf, d);
        float pb = __shfl_up_sync(full, iBf, d);
        float qa = __shfl_up_sync(full, iAs, d);
        float qb = __shfl_up_sync(full, iBs, d);
        if (lane >= d) {
            iBf = iAf * pb + iBf;  iAf *= pa;
            iBs = iAs * qb + iBs;  iAs *= qa;
        }
    }
    float eAf = __shfl_up_sync(full, iAf, 1), eBf = __shfl_up_sync(full, iBf, 1);
    float eAs = __shfl_up_sync(full, iAs, 1), eBs = __shfl_up_sync(full, iBs, 1);
    if (lane == 0) { eAf = 1.0f; eBf = 0.0f; eAs = 1.0f; eBs = 0.0f; }
    if (lane == 31) {
        scn[warp] = iAf; scn[8 + warp] = iBf; scn[16 + warp] = iAs; scn[24 + warp] = iBs;
    }
    __syncthreads();
    float pBf = 0.0f, pBs = 0.0f;
    for (int w = 0; w < warp; w++) {
        pBf = scn[w] * pBf + scn[8 + w];
        pBs = scn[16 + w] * pBs + scn[24 + w];
    }
    float accf = eAf * pBf + eBf;
    float accs = eAs * pBs + eBs;
    for (int i = 0; i < CH; i++) {
        int e = tid * CH + i;
        if (e < E) {
            float g = sga[e];
            accf = 0.8f  * accf + 0.2f  * g;
            accs = 0.95f * accs + 0.05f * g;
            sqf[e] = accf; sqs[e] = accs;
        }
    }
    __syncthreads();
    const size_t base = (size_t)row * T_ + t0;
    const int off = t0 - ts;
    for (int i = tid; i < 2048; i += 256) {
        qfs_o[base + i] = make_float2(sqf[off + i], sqs[off + i]);
    }
}

// ---------------------------------------------------------------------------
// Persistent main kernel: 148 blocks x 1024 threads, 256-row tiles.
// Feats DOUBLE-BUFFERED across tiles: features for tile t+148 are computed
// inside tile t's q==0 slot, overlapping LDG latency with MMA work.
// h1 quartered + double-buffered; stage1(q+1) pipelined with stage2(q).
// ---------------------------------------------------------------------------
// smem byte offsets
#define SM_FS  0                      // 2 bufs x (hi 12288 + lo 12288) = 49152
#define SM_W1H 49152                  // 6144
#define SM_W1L 55296                  // 6144
#define SM_W2H 61440                  // 34816
#define SM_W2L 96256                  // 34816
#define SM_H1H 131072                 // 2 x 20480
#define SM_H1L 172032                 // 2 x 20480
#define SM_B1  212992                 // 512
#define SM_B2  213504                 // 512
#define SM_TOT 214016

__global__ void __launch_bounds__(1024, 1) mlp_kernel(
    const float* __restrict__ gaze,
    const float* __restrict__ lwx, const float* __restrict__ phx,
    const float* __restrict__ lwy, const float* __restrict__ phy,
    const float* __restrict__ p_logthr, const float* __restrict__ p_invT,
    const float2* __restrict__ qfs_i,
    const float* __restrict__ b1, const float* __restrict__ b2,
    float* __restrict__ out)
{
    extern __shared__ char smem[];
    const uint32_t sbase = (uint32_t)__cvta_generic_to_shared(smem);
    float* b1s = reinterpret_cast<float*>(smem + SM_B1);
    float* b2s = reinterpret_cast<float*>(smem + SM_B2);

    const int tid = threadIdx.x;

    // ---- one-time staging ----
    for (int c = tid; c < 2176; c += 1024) {
        cpasync16(sbase + SM_W2H + c * 16, (const char*)g_w2h + c * 16);
        cpasync16(sbase + SM_W2L + c * 16, (const char*)g_w2l + c * 16);
    }
    if (tid < 384) {
        cpasync16(sbase + SM_W1H + tid * 16, (const char*)g_w1h + tid * 16);
        cpasync16(sbase + SM_W1L + tid * 16, (const char*)g_w1l + tid * 16);
    }
    asm volatile("cp.async.commit_group;");
    if (tid < 128) { b1s[tid] = b1[tid]; b2s[tid] = b2[tid]; }
    if (tid < 256) {
        // K-pad cols 20..23 zero in both buffers, both planes (constant)
#pragma unroll
        for (int b = 0; b < 2; b++) {
            uint32_t* fh = reinterpret_cast<uint32_t*>(smem + SM_FS + b * 24576);
            uint32_t* fl = reinterpret_cast<uint32_t*>(smem + SM_FS + b * 24576 + 12288);
            fh[tid * 12 + 10] = 0; fh[tid * 12 + 11] = 0;
            fl[tid * 12 + 10] = 0; fl[tid * 12 + 11] = 0;
        }
    }
    asm volatile("cp.async.wait_group 0;");

    const int lane = tid & 31, warp = tid >> 5;
    const int g  = lane >> 2, tg = lane & 3;
    const int rg = warp >> 2, cg = warp & 3;

    const int t4  = lane >> 3;
    const int tr4 = lane & 7;
    const int r4  = (t4 & 1) * 8 + tr4;
    const int k4  = (t4 >> 1) * 16;
    const int r2  = ((lane >> 3) & 1) * 8 + tr4;
    const int rB2 = lane & 7;
    const int kB2 = ((lane >> 3) & 1) * 16;

    const float inv_dt = 240.0f;
    const float twopi  = 6.283185307179586f;
    const float wx0 = __expf(lwx[0]), wx1 = __expf(lwx[1]);
    const float wy0 = __expf(lwy[0]), wy1 = __expf(lwy[1]);
    const float px0 = phx[0], px1 = phx[1], py0 = phy[0], py1 = phy[1];
    const float thr  = __expf(p_logthr[0]);
    const float invT = p_invT[0];

    // feature generator for tile tl into feats buffer fb2 (tid < 512 only)
    auto make_feats = [&](int tl, int fb2) {
        const int bIdx = tl >> 5;
        const int tt0  = (tl & 31) << 8;
        const int row = tid >> 1, sub = tid & 1;
        uint32_t* fh = reinterpret_cast<uint32_t*>(smem + SM_FS + fb2 * 24576);
        uint32_t* fl = reinterpret_cast<uint32_t*>(smem + SM_FS + fb2 * 24576 + 12288);
        const float2* gz = reinterpret_cast<const float2*>(gaze) + (size_t)bIdx * T_;
        const int t = tt0 + row;
        const size_t idx = (size_t)bIdx * T_ + t;
        float2 xc = gz[t];
        float2 x1 = gz[max(t - 1, 0)];
        float2 x2 = gz[max(t - 2, 0)];
        float vx  = (xc.x - x1.x) * inv_dt;
        float vy  = (xc.y - x1.y) * inv_dt;
        float ax  = (vx - (x1.x - x2.x) * inv_dt) * inv_dt;
        float ay  = (vy - (x1.y - x2.y) * inv_dt) * inv_dt;
        float sp  = sqrtf(vx * vx + vy * vy);
        float isp = 1.0f / (sp + 1e-6f);
        uint32_t hi, lo;
        if (sub == 0) {
            float s0, c0, s1, c1;
            __sincosf(fmaf(twopi * wx0, xc.x, px0), &s0, &c0);
            __sincosf(fmaf(twopi * wx1, xc.x, px1), &s1, &c1);
            split2_bf16(s0, s1, hi, lo); fh[row*12+0] = hi; fl[row*12+0] = lo;
            split2_bf16(c0, c1, hi, lo); fh[row*12+1] = hi; fl[row*12+1] = lo;
            split2_bf16(vx, vy, hi, lo); fh[row*12+4] = hi; fl[row*12+4] = lo;
            split2_bf16(sp, vx*isp, hi, lo); fh[row*12+5] = hi; fl[row*12+5] = lo;
        } else {
            float u0, d0, u1, d1;
            __sincosf(fmaf(twopi * wy0, xc.y, py0), &u0, &d0);
            __sincosf(fmaf(twopi * wy1, xc.y, py1), &u1, &d1);
            float2 qq = qfs_i[idx];
            float gate = sigmoid_fast(invT * (sp - thr));
            split2_bf16(u0, u1, hi, lo); fh[row*12+2] = hi; fl[row*12+2] = lo;
            split2_bf16(d0, d1, hi, lo); fh[row*12+3] = hi; fl[row*12+3] = lo;
            split2_bf16(vy*isp, ax, hi, lo); fh[row*12+6] = hi; fl[row*12+6] = lo;
            split2_bf16(ay, (vx*ax+vy*ay)*isp, hi, lo); fh[row*12+7] = hi; fl[row*12+7] = lo;
            split2_bf16((vx*ay-vy*ax)*isp, gate, hi, lo); fh[row*12+8] = hi; fl[row*12+8] = lo;
            split2_bf16(qq.x, qq.y, hi, lo); fh[row*12+9] = hi; fl[row*12+9] = lo;
        }
    };

    auto stage1 = [&](int q, int buf, int fb2) {
        const int nB1 = q * 32 + cg * 8;
        const uint32_t fsh = sbase + SM_FS + fb2 * 24576;
        const uint32_t fsl = fsh + 12288;
        uint32_t* h1h = reinterpret_cast<uint32_t*>(smem + SM_H1H + buf * 20480);
        uint32_t* h1l = reinterpret_cast<uint32_t*>(smem + SM_H1L + buf * 20480);
        uint32_t B1h[3], B1l[3];
        ldsm2(&B1h[0], sbase + SM_W1H + (nB1 + tr4) * 48 + ((lane >> 3) & 1) * 16);
        ldsm2(&B1l[0], sbase + SM_W1L + (nB1 + tr4) * 48 + ((lane >> 3) & 1) * 16);
        ldsm1(&B1h[2], sbase + SM_W1H + (nB1 + tr4) * 48 + 32);
        ldsm1(&B1l[2], sbase + SM_W1L + (nB1 + tr4) * 48 + 32);
#pragma unroll
        for (int mt = 0; mt < 2; mt++) {
            const int rA = rg * 32 + mt * 16;
            uint32_t A1h[6], A1l[6];
            ldsm4(&A1h[0], fsh + (rA + r4) * 48 + k4);
            ldsm4(&A1l[0], fsl + (rA + r4) * 48 + k4);
            ldsm2(&A1h[4], fsh + (rA + r2) * 48 + 32);
            ldsm2(&A1l[4], fsl + (rA + r2) * 48 + 32);
            float acc1[4];
            acc1[0] = b1s[nB1 + 2 * tg];  acc1[1] = b1s[nB1 + 2 * tg + 1];
            acc1[2] = acc1[0];            acc1[3] = acc1[1];
            mma16(acc1, &A1h[0], &B1h[0]);
            mma16(acc1, &A1h[0], &B1l[0]);
            mma16(acc1, &A1l[0], &B1h[0]);
            mma8b(acc1, &A1h[4], &B1h[2]);
            mma8b(acc1, &A1h[4], &B1l[2]);
            mma8b(acc1, &A1l[4], &B1h[2]);
            int row = rA + g;
            int widx = row * 20 + cg * 4 + tg;
            uint32_t hi, lo;
            split2_bf16(gelu_fast(acc1[0]), gelu_fast(acc1[1]), hi, lo);
            h1h[widx] = hi;  h1l[widx] = lo;
            split2_bf16(gelu_fast(acc1[2]), gelu_fast(acc1[3]), hi, lo);
            h1h[widx + 160] = hi;  h1l[widx + 160] = lo;
        }
    };

    // ---- prologue: features for first tile ----
    __syncthreads();
    if (tid < 512) make_feats(blockIdx.x, 0);
    __syncthreads();

    int fb = 0;
    for (int tile = blockIdx.x; tile < NTILES2; tile += NBLK) {
        float acc2[2][4][4];
#pragma unroll
        for (int mt = 0; mt < 2; mt++)
#pragma unroll
            for (int nt = 0; nt < 4; nt++) {
                int col = cg * 32 + nt * 8 + 2 * tg;
                acc2[mt][nt][0] = b2s[col];  acc2[mt][nt][1] = b2s[col + 1];
                acc2[mt][nt][2] = acc2[mt][nt][0];
                acc2[mt][nt][3] = acc2[mt][nt][1];
            }

        stage1(0, 0, fb);
        __syncthreads();

#pragma unroll 1
        for (int q = 0; q < 4; q++) {
            if (q < 3) stage1(q + 1, (q + 1) & 1, fb);
            if (q == 0 && tid < 512 && tile + NBLK < NTILES2)
                make_feats(tile + NBLK, fb ^ 1);
            const int rbuf = q & 1;
#pragma unroll
            for (int kc = 0; kc < 2; kc++) {
                uint32_t Ah[2][4], Al[2][4];
#pragma unroll
                for (int mt = 0; mt < 2; mt++) {
                    int rA = rg * 32 + mt * 16 + r4;
                    ldsm4(Ah[mt], sbase + SM_H1H + rbuf * 20480 + rA * 80 + kc * 32 + k4);
                    ldsm4(Al[mt], sbase + SM_H1L + rbuf * 20480 + rA * 80 + kc * 32 + k4);
                }
                uint32_t Bh[4][2], Bl[4][2];
#pragma unroll
                for (int nt = 0; nt < 4; nt++) {
                    int nB = cg * 32 + nt * 8 + rB2;
                    ldsm2(Bh[nt], sbase + SM_W2H + nB * 272 + q * 64 + kc * 32 + kB2);
                    ldsm2(Bl[nt], sbase + SM_W2L + nB * 272 + q * 64 + kc * 32 + kB2);
                }
#pragma unroll
                for (int nt = 0; nt < 4; nt++)
#pragma unroll
                    for (int mt = 0; mt < 2; mt++)
                        mma16(acc2[mt][nt], Ah[mt], Bh[nt]);
#pragma unroll
                for (int nt = 0; nt < 4; nt++)
#pragma unroll
                    for (int mt = 0; mt < 2; mt++)
                        mma16(acc2[mt][nt], Ah[mt], Bl[nt]);
#pragma unroll
                for (int nt = 0; nt < 4; nt++)
#pragma unroll
                    for (int mt = 0; mt < 2; mt++)
                        mma16(acc2[mt][nt], Al[mt], Bh[nt]);
            }
            __syncthreads();
        }

        // ---- final epilogue (registers only) ----
        const size_t r0 = (size_t)tile * 256;
#pragma unroll
        for (int mt = 0; mt < 2; mt++)
#pragma unroll
            for (int nt = 0; nt < 4; nt++) {
                int r = rg * 32 + mt * 16 + g;
                int c = cg * 32 + nt * 8 + 2 * tg;
                float2 v0 = make_float2(gelu_fast(acc2[mt][nt][0]), gelu_fast(acc2[mt][nt][1]));
                float2 v1 = make_float2(gelu_fast(acc2[mt][nt][2]), gelu_fast(acc2[mt][nt][3]));
                *reinterpret_cast<float2*>(out + (r0 + r) * 128 + c)     = v0;
                *reinterpret_cast<float2*>(out + (r0 + r + 8) * 128 + c) = v1;
            }
        fb ^= 1;
    }
}

// ---------------------------------------------------------------------------
extern "C" void kernel_launch(void* const* d_in, const int* in_sizes, int n_in,
                              void* d_out, int out_size)
{
    const float* gaze   = (const float*)d_in[0];
    const float* lwx    = (const float*)d_in[1];
    const float* phx    = (const float*)d_in[2];
    const float* lwy    = (const float*)d_in[3];
    const float* phy    = (const float*)d_in[4];
    const float* logthr = (const float*)d_in[5];
    const float* invT   = (const float*)d_in[6];
    const float* W1     = (const float*)d_in[7];
    const float* b1     = (const float*)d_in[8];
    const float* W2     = (const float*)d_in[9];
    const float* b2     = (const float*)d_in[10];
    float* out = (float*)d_out;

    float2* qfs;
    cudaGetSymbolAddress((void**)&qfs, g_qfs);

    const size_t smemA = (size_t)(5124 + 3 * 2560 + 32) * sizeof(float);
    cudaFuncSetAttribute(ema_kernel,
                         cudaFuncAttributeMaxDynamicSharedMemorySize, (int)smemA);
    ema_kernel<<<B_ * 4, 256, smemA>>>(gaze, logthr, invT, W1, W2, qfs);

    cudaFuncSetAttribute(mlp_kernel,
                         cudaFuncAttributeMaxDynamicSharedMemorySize, SM_TOT);
    mlp_kernel<<<NBLK, 1024, SM_TOT>>>(
        gaze, lwx, phx, lwy, phy, logthr, invT, qfs, b1, b2, out);
}

// round 16
// speedup vs baseline: 1.3729x; 1.3729x over previous
#include <cuda_runtime.h>
#include <cuda_fp16.h>
#include <cuda_bf16.h>
#include <stdint.h>
#include <math.h>

#define B_    64
#define T_    8192
#define DIN   20
#define NROWS ((size_t)B_ * T_)
#define WARM  512
#define NTILES2 2048
#define NBLK   148

#define S_H    0.001953125f   // 2^-9 h1 scale
#define INV_SH 512.0f
#define S_V    0.25f          // velocity-ish columns
#define S_A    0.00390625f    // 2^-8 accel-ish columns

// device scratch: packed (q_fast, q_slow)
__device__ float2 g_qfs[NROWS];
// fp16 weight planes (single plane each; W1 rows pre-scaled by 1/S_col)
__device__ __align__(16) __half g_w1[128 * 24];     // [n][k] 48B rows
__device__ __align__(16) __half g_w2[128 * 136];    // [n][k] 272B rows

// ---------------------------------------------------------------------------
__device__ __forceinline__ void mma16(float* d, const uint32_t* a, const uint32_t* b) {
    asm("mma.sync.aligned.m16n8k16.row.col.f32.f16.f16.f32 "
        "{%0,%1,%2,%3}, {%4,%5,%6,%7}, {%8,%9}, {%0,%1,%2,%3};"
        : "+f"(d[0]), "+f"(d[1]), "+f"(d[2]), "+f"(d[3])
        : "r"(a[0]), "r"(a[1]), "r"(a[2]), "r"(a[3]), "r"(b[0]), "r"(b[1]));
}
__device__ __forceinline__ void mma8(float* d, const uint32_t* a, const uint32_t* b) {
    asm("mma.sync.aligned.m16n8k8.row.col.f32.f16.f16.f32 "
        "{%0,%1,%2,%3}, {%4,%5}, {%6}, {%0,%1,%2,%3};"
        : "+f"(d[0]), "+f"(d[1]), "+f"(d[2]), "+f"(d[3])
        : "r"(a[0]), "r"(a[1]), "r"(b[0]));
}
__device__ __forceinline__ void ldsm4(uint32_t* R, uint32_t addr) {
    asm volatile("ldmatrix.sync.aligned.m8n8.x4.shared.b16 {%0,%1,%2,%3},[%4];"
        : "=r"(R[0]), "=r"(R[1]), "=r"(R[2]), "=r"(R[3]) : "r"(addr));
}
__device__ __forceinline__ void ldsm2(uint32_t* R, uint32_t addr) {
    asm volatile("ldmatrix.sync.aligned.m8n8.x2.shared.b16 {%0,%1},[%2];"
        : "=r"(R[0]), "=r"(R[1]) : "r"(addr));
}
__device__ __forceinline__ void ldsm1(uint32_t* R, uint32_t addr) {
    asm volatile("ldmatrix.sync.aligned.m8n8.x1.shared.b16 {%0},[%1];"
        : "=r"(R[0]) : "r"(addr));
}
__device__ __forceinline__ void cpasync16(uint32_t saddr, const void* g) {
    asm volatile("cp.async.cg.shared.global [%0], [%1], 16;" :: "r"(saddr), "l"(g));
}
__device__ __forceinline__ float gelu_fast(float x) {
    float x2   = x * x;
    float q    = fmaf(-0.10294419f, x2, -2.3021177f);
    float narg = x * q;
    float e2;
    asm("ex2.approx.f32 %0, %1;" : "=f"(e2) : "f"(narg));
    float d = 1.0f + e2;
    float r;
    asm("rcp.approx.f32 %0, %1;" : "=f"(r) : "f"(d));
    return x * r;
}
__device__ __forceinline__ float sigmoid_fast(float x) {
    float e2;
    asm("ex2.approx.f32 %0, %1;" : "=f"(e2) : "f"(-1.4426950408889634f * x));
    float r;
    asm("rcp.approx.f32 %0, %1;" : "=f"(r) : "f"(1.0f + e2));
    return r;
}
// fp16 hi/lo split of a float pair (x0 -> low half, x1 -> high half)
__device__ __forceinline__ void split2_f16(float x0, float x1,
                                           uint32_t& hi, uint32_t& lo) {
    __half2 h = __floats2half2_rn(x0, x1);
    float h0 = __half2float(__low2half(h));
    float h1f = __half2float(__high2half(h));
    __half2 l = __floats2half2_rn(x0 - h0, x1 - h1f);
    hi = *reinterpret_cast<uint32_t*>(&h);
    lo = *reinterpret_cast<uint32_t*>(&l);
}

// ---------------------------------------------------------------------------
// Kernel A: gate + EMA + folded fp16 weight prep (W1 rows scaled by 1/S_col).
// ---------------------------------------------------------------------------
__global__ void __launch_bounds__(256) ema_kernel(
    const float* __restrict__ gaze,
    const float* __restrict__ p_logthr, const float* __restrict__ p_invT,
    const float* __restrict__ W1, const float* __restrict__ W2,
    float2* __restrict__ qfs_o)
{
    extern __shared__ float sm[];
    float2* sg  = reinterpret_cast<float2*>(sm);
    float*  sga = sm + 5124;
    float*  sqf = sga + 2560;
    float*  sqs = sqf + 2560;
    float*  scn = sqs + 2560;

    const int tid = threadIdx.x;

    {   // weight prep
        int i = blockIdx.x * 256 + tid;
        if (i < 128 * 136) {
            int n = i / 136, k = i - n * 136;
            float v = (k < 128) ? W2[k * 128 + n] : 0.0f;
            g_w2[i] = __float2half_rn(v);
        }
        if (i < 128 * 24) {
            int n = i / 24, k = i - n * 24;
            float s = 1.0f;
            if (k >= 8 && k <= 10) s = 1.0f / S_V;
            else if (k >= 13 && k <= 16) s = 1.0f / S_A;
            float v = (k < DIN) ? W1[k * 128 + n] * s : 0.0f;
            g_w1[i] = __float2half_rn(v);
        }
    }

    const int row = blockIdx.x >> 2;
    const int t0  = (blockIdx.x & 3) * 2048;
    const int ts  = max(t0 - WARM, 0);
    const int ts2 = max(ts - 1, 0);
    const int E   = t0 + 2048 - ts;
    const int NG  = t0 + 2048 - ts2;
    const int hof = ts - ts2;

    const float2* gz = reinterpret_cast<const float2*>(gaze) + (size_t)row * T_;
    for (int i = tid; i < NG; i += 256) sg[i] = gz[ts2 + i];
    const float thr  = expf(p_logthr[0]);
    const float invT = p_invT[0];
    const float inv_dt = 240.0f;
    __syncthreads();

    const int CH = (E + 255) >> 8;
    float Af = 1.0f, Bf = 0.0f, As = 1.0f, Bs = 0.0f;
    for (int i = 0; i < CH; i++) {
        int e = tid * CH + i;
        if (e < E) {
            int j = e + hof;
            float2 xc = sg[j];
            float2 x1 = sg[max(j - 1, 0)];
            float vx = (xc.x - x1.x) * inv_dt;
            float vy = (xc.y - x1.y) * inv_dt;
            float sp = sqrtf(vx * vx + vy * vy);
            float g  = 1.0f / (1.0f + expf(-invT * (sp - thr)));
            sga[e] = g;
            Bf = 0.8f  * Bf + 0.2f  * g;  Af *= 0.8f;
            Bs = 0.95f * Bs + 0.05f * g;  As *= 0.95f;
        }
    }
    const unsigned full = 0xffffffffu;
    const int lane = tid & 31, warp = tid >> 5;
    float iAf = Af, iBf = Bf, iAs = As, iBs = Bs;
#pragma unroll
    for (int d = 1; d < 32; d <<= 1) {
        float pa = __shfl_up_sync(full, iAf, d);
        float pb = __shfl_up_sync(full, iBf, d);
        float qa = __shfl_up_sync(full, iAs, d);
        float qb = __shfl_up_sync(full, iBs, d);
        if (lane >= d) {
            iBf = iAf * pb + iBf;  iAf *= pa;
            iBs = iAs * qb + iBs;  iAs *= qa;
        }
    }
    float eAf = __shfl_up_sync(full, iAf, 1), eBf = __shfl_up_sync(full, iBf, 1);
    float eAs = __shfl_up_sync(full, iAs, 1), eBs = __shfl_up_sync(full, iBs, 1);
    if (lane == 0) { eAf = 1.0f; eBf = 0.0f; eAs = 1.0f; eBs = 0.0f; }
    if (lane == 31) {
        scn[warp] = iAf; scn[8 + warp] = iBf; scn[16 + warp] = iAs; scn[24 + warp] = iBs;
    }
    __syncthreads();
    float pBf = 0.0f, pBs = 0.0f;
    for (int w = 0; w < warp; w++) {
        pBf = scn[w] * pBf + scn[8 + w];
        pBs = scn[16 + w] * pBs + scn[24 + w];
    }
    float accf = eAf * pBf + eBf;
    float accs = eAs * pBs + eBs;
    for (int i = 0; i < CH; i++) {
        int e = tid * CH + i;
        if (e < E) {
            float g = sga[e];
            accf = 0.8f  * accf + 0.2f  * g;
            accs = 0.95f * accs + 0.05f * g;
            sqf[e] = accf; sqs[e] = accs;
        }
    }
    __syncthreads();
    const size_t base = (size_t)row * T_ + t0;
    const int off = t0 - ts;
    for (int i = tid; i < 2048; i += 256) {
        qfs_o[base + i] = make_float2(sqf[off + i], sqs[off + i]);
    }
}

// ---------------------------------------------------------------------------
// Persistent main kernel: 148 blocks x 1024 threads, 256-row tiles.
// fp16 2-product split (A hi/lo, W single plane). Full h1 tile in smem:
// stage2 runs as one unbroken MMA stream; only 2 barriers per tile.
// ---------------------------------------------------------------------------
// smem byte offsets
#define SM_FSH 0                      // feats hi [256][24] f16 = 12288
#define SM_FSL 12288                  // feats lo
#define SM_W1  24576                  // W1 [128][24] f16 = 6144
#define SM_W2  30720                  // W2 [128][136] f16 = 34816
#define SM_H1H 65536                  // h1 hi [256][136] f16 = 69632
#define SM_H1L 135168                 // h1 lo
#define SM_B1  204800                 // 512
#define SM_B2  205312                 // 512 (pre-scaled by S_H)
#define SM_TOT 205824

__global__ void __launch_bounds__(1024, 1) mlp_kernel(
    const float* __restrict__ gaze,
    const float* __restrict__ lwx, const float* __restrict__ phx,
    const float* __restrict__ lwy, const float* __restrict__ phy,
    const float* __restrict__ p_logthr, const float* __restrict__ p_invT,
    const float2* __restrict__ qfs_i,
    const float* __restrict__ b1, const float* __restrict__ b2,
    float* __restrict__ out)
{
    extern __shared__ char smem[];
    const uint32_t sbase = (uint32_t)__cvta_generic_to_shared(smem);
    uint32_t* fshw = reinterpret_cast<uint32_t*>(smem + SM_FSH);
    uint32_t* fslw = reinterpret_cast<uint32_t*>(smem + SM_FSL);
    uint32_t* h1hw = reinterpret_cast<uint32_t*>(smem + SM_H1H);
    uint32_t* h1lw = reinterpret_cast<uint32_t*>(smem + SM_H1L);
    float* b1s = reinterpret_cast<float*>(smem + SM_B1);
    float* b2s = reinterpret_cast<float*>(smem + SM_B2);

    const int tid = threadIdx.x;

    // ---- one-time staging ----
    for (int c = tid; c < 2176; c += 1024)
        cpasync16(sbase + SM_W2 + c * 16, (const char*)g_w2 + c * 16);
    if (tid < 384)
        cpasync16(sbase + SM_W1 + tid * 16, (const char*)g_w1 + tid * 16);
    asm volatile("cp.async.commit_group;");
    if (tid < 128) { b1s[tid] = b1[tid]; b2s[tid] = b2[tid] * S_H; }
    if (tid < 256) {   // zero K-pad words (cols 20..23) of feats planes
        fshw[tid * 12 + 10] = 0; fshw[tid * 12 + 11] = 0;
        fslw[tid * 12 + 10] = 0; fslw[tid * 12 + 11] = 0;
    }
    asm volatile("cp.async.wait_group 0;");
    __syncthreads();

    const int lane = tid & 31, warp = tid >> 5;
    const int g  = lane >> 2, tg = lane & 3;
    const int rg = warp >> 2, cg = warp & 3;

    const int t4  = lane >> 3;
    const int tr4 = lane & 7;
    const int r4  = (t4 & 1) * 8 + tr4;           // A x4 row offset
    const int k4  = (t4 >> 1) * 16;               // A x4 k-byte offset
    const int r2  = ((lane >> 3) & 1) * 8 + tr4;  // A x2 row
    const int rB2 = lane & 7;                     // B x2 n row
    const int kB2 = ((lane >> 3) & 1) * 16;       // B x2 k-byte

    const float inv_dt = 240.0f;
    const float twopi  = 6.283185307179586f;
    const float wx0 = __expf(lwx[0]), wx1 = __expf(lwx[1]);
    const float wy0 = __expf(lwy[0]), wy1 = __expf(lwy[1]);
    const float px0 = phx[0], px1 = phx[1], py0 = phy[0], py1 = phy[1];
    const float thr  = __expf(p_logthr[0]);
    const float invT = p_invT[0];

    for (int tile = blockIdx.x; tile < NTILES2; tile += NBLK) {
        const int bIdx = tile >> 5;
        const int t0   = (tile & 31) << 8;

        // ---- features: 512 threads, 2 per row, scaled columns ----
        if (tid < 512) {
            const int row = tid >> 1, sub = tid & 1;
            const float2* gz = reinterpret_cast<const float2*>(gaze) + (size_t)bIdx * T_;
            const int t = t0 + row;
            const size_t idx = (size_t)bIdx * T_ + t;
            float2 xc = gz[t];
            float2 x1 = gz[max(t - 1, 0)];
            float2 x2 = gz[max(t - 2, 0)];
            float vx  = (xc.x - x1.x) * inv_dt;
            float vy  = (xc.y - x1.y) * inv_dt;
            float ax  = (vx - (x1.x - x2.x) * inv_dt) * inv_dt;
            float ay  = (vy - (x1.y - x2.y) * inv_dt) * inv_dt;
            float sp  = sqrtf(vx * vx + vy * vy);
            float isp = 1.0f / (sp + 1e-6f);
            uint32_t hi, lo;
            if (sub == 0) {
                float s0, c0, s1, c1;
                __sincosf(fmaf(twopi * wx0, xc.x, px0), &s0, &c0);
                __sincosf(fmaf(twopi * wx1, xc.x, px1), &s1, &c1);
                split2_f16(s0, s1, hi, lo); fshw[row*12+0] = hi; fslw[row*12+0] = lo;
                split2_f16(c0, c1, hi, lo); fshw[row*12+1] = hi; fslw[row*12+1] = lo;
                split2_f16(vx * S_V, vy * S_V, hi, lo); fshw[row*12+4] = hi; fslw[row*12+4] = lo;
                split2_f16(sp * S_V, vx * isp, hi, lo); fshw[row*12+5] = hi; fslw[row*12+5] = lo;
            } else {
                float u0, d0, u1, d1;
                __sincosf(fmaf(twopi * wy0, xc.y, py0), &u0, &d0);
                __sincosf(fmaf(twopi * wy1, xc.y, py1), &u1, &d1);
                float2 qq = qfs_i[idx];
                float gate = sigmoid_fast(invT * (sp - thr));
                split2_f16(u0, u1, hi, lo); fshw[row*12+2] = hi; fslw[row*12+2] = lo;
                split2_f16(d0, d1, hi, lo); fshw[row*12+3] = hi; fslw[row*12+3] = lo;
                split2_f16(vy * isp, ax * S_A, hi, lo); fshw[row*12+6] = hi; fslw[row*12+6] = lo;
                split2_f16(ay * S_A, (vx*ax + vy*ay) * isp * S_A, hi, lo);
                fshw[row*12+7] = hi; fslw[row*12+7] = lo;
                split2_f16((vx*ay - vy*ax) * isp * S_A, gate, hi, lo);
                fshw[row*12+8] = hi; fslw[row*12+8] = lo;
                split2_f16(qq.x, qq.y, hi, lo); fshw[row*12+9] = hi; fslw[row*12+9] = lo;
            }
        }
        __syncthreads();   // sync 1: feats ready (also protects h1 vs prev tile)

        // ---- stage 1 (single pass): h1 = gelu(feats @ W1 + b1) * S_H ----
        {
            uint32_t A1h[2][6], A1l[2][6];
#pragma unroll
            for (int mt = 0; mt < 2; mt++) {
                const int rA = rg * 32 + mt * 16;
                ldsm4(&A1h[mt][0], sbase + SM_FSH + (rA + r4) * 48 + k4);
                ldsm4(&A1l[mt][0], sbase + SM_FSL + (rA + r4) * 48 + k4);
                ldsm2(&A1h[mt][4], sbase + SM_FSH + (rA + r2) * 48 + 32);
                ldsm2(&A1l[mt][4], sbase + SM_FSL + (rA + r2) * 48 + 32);
            }
#pragma unroll
            for (int nt = 0; nt < 4; nt++) {
                const int nB1 = cg * 32 + nt * 8;
                uint32_t B1[3];
                ldsm2(&B1[0], sbase + SM_W1 + (nB1 + tr4) * 48 + ((lane >> 3) & 1) * 16);
                ldsm1(&B1[2], sbase + SM_W1 + (nB1 + tr4) * 48 + 32);
#pragma unroll
                for (int mt = 0; mt < 2; mt++) {
                    float acc1[4];
                    acc1[0] = b1s[nB1 + 2 * tg];  acc1[1] = b1s[nB1 + 2 * tg + 1];
                    acc1[2] = acc1[0];            acc1[3] = acc1[1];
                    mma16(acc1, &A1h[mt][0], &B1[0]);
                    mma16(acc1, &A1l[mt][0], &B1[0]);
                    mma8(acc1, &A1h[mt][4], &B1[2]);
                    mma8(acc1, &A1l[mt][4], &B1[2]);
                    int row = rg * 32 + mt * 16 + g;
                    int widx = row * 68 + ((nB1 + 2 * tg) >> 1);
                    uint32_t hi, lo;
                    split2_f16(gelu_fast(acc1[0]) * S_H, gelu_fast(acc1[1]) * S_H, hi, lo);
                    h1hw[widx] = hi;  h1lw[widx] = lo;
                    split2_f16(gelu_fast(acc1[2]) * S_H, gelu_fast(acc1[3]) * S_H, hi, lo);
                    h1hw[widx + 8 * 68] = hi;  h1lw[widx + 8 * 68] = lo;
                }
            }
        }
        __syncthreads();   // sync 2: h1 complete

        // ---- stage 2: unbroken MMA stream over full K=128 ----
        float acc2[2][4][4];
#pragma unroll
        for (int mt = 0; mt < 2; mt++)
#pragma unroll
            for (int nt = 0; nt < 4; nt++) {
                int col = cg * 32 + nt * 8 + 2 * tg;
                acc2[mt][nt][0] = b2s[col];  acc2[mt][nt][1] = b2s[col + 1];
                acc2[mt][nt][2] = acc2[mt][nt][0];
                acc2[mt][nt][3] = acc2[mt][nt][1];
            }

#pragma unroll 1
        for (int kc8 = 0; kc8 < 8; kc8++) {       // 16 K per iter
            const int kb = kc8 * 32;              // k byte offset
            uint32_t Ah[2][4], Al[2][4];
#pragma unroll
            for (int mt = 0; mt < 2; mt++) {
                int rA = rg * 32 + mt * 16 + r4;
                ldsm4(Ah[mt], sbase + SM_H1H + rA * 272 + kb + k4);
                ldsm4(Al[mt], sbase + SM_H1L + rA * 272 + kb + k4);
            }
#pragma unroll
            for (int nt = 0; nt < 4; nt++) {
                int nB = cg * 32 + nt * 8 + rB2;
                uint32_t Bq[2];
                ldsm2(Bq, sbase + SM_W2 + nB * 272 + kb + kB2);
#pragma unroll
                for (int mt = 0; mt < 2; mt++) {
                    mma16(acc2[mt][nt], Ah[mt], Bq);
                    mma16(acc2[mt][nt], Al[mt], Bq);
                }
            }
        }

        // ---- epilogue: unscale, gelu, store ----
        const size_t r0 = (size_t)tile * 256;
#pragma unroll
        for (int mt = 0; mt < 2; mt++)
#pragma unroll
            for (int nt = 0; nt < 4; nt++) {
                int r = rg * 32 + mt * 16 + g;
                int c = cg * 32 + nt * 8 + 2 * tg;
                float2 v0 = make_float2(gelu_fast(acc2[mt][nt][0] * INV_SH),
                                        gelu_fast(acc2[mt][nt][1] * INV_SH));
                float2 v1 = make_float2(gelu_fast(acc2[mt][nt][2] * INV_SH),
                                        gelu_fast(acc2[mt][nt][3] * INV_SH));
                *reinterpret_cast<float2*>(out + (r0 + r) * 128 + c)     = v0;
                *reinterpret_cast<float2*>(out + (r0 + r + 8) * 128 + c) = v1;
            }
    }
}

// ---------------------------------------------------------------------------
extern "C" void kernel_launch(void* const* d_in, const int* in_sizes, int n_in,
                              void* d_out, int out_size)
{
    const float* gaze   = (const float*)d_in[0];
    const float* lwx    = (const float*)d_in[1];
    const float* phx    = (const float*)d_in[2];
    const float* lwy    = (const float*)d_in[3];
    const float* phy    = (const float*)d_in[4];
    const float* logthr = (const float*)d_in[5];
    const float* invT   = (const float*)d_in[6];
    const float* W1     = (const float*)d_in[7];
    const float* b1     = (const float*)d_in[8];
    const float* W2     = (const float*)d_in[9];
    const float* b2     = (const float*)d_in[10];
    float* out = (float*)d_out;

    float2* qfs;
    cudaGetSymbolAddress((void**)&qfs, g_qfs);

    const size_t smemA = (size_t)(5124 + 3 * 2560 + 32) * sizeof(float);
    cudaFuncSetAttribute(ema_kernel,
                         cudaFuncAttributeMaxDynamicSharedMemorySize, (int)smemA);
    ema_kernel<<<B_ * 4, 256, smemA>>>(gaze, logthr, invT, W1, W2, qfs);

    cudaFuncSetAttribute(mlp_kernel,
                         cudaFuncAttributeMaxDynamicSharedMemorySize, SM_TOT);
    mlp_kernel<<<NBLK, 1024, SM_TOT>>>(
        gaze, lwx, phx, lwy, phy, logthr, invT, qfs, b1, b2, out);
}